// round 2
// baseline (speedup 1.0000x reference)
#include <cuda_runtime.h>
#include <math.h>

#define T_LEN 4096
#define C_DIM 2048
#define NH    16
#define NKV   4
#define HD    128
#define WW    1024
#define NB    4

// ---------------- scratch (device globals; no runtime alloc) ----------------
__device__ float g_Q[T_LEN * C_DIM];        // 33.5 MB
__device__ float g_K[T_LEN * NKV * HD];     //  8.4 MB
__device__ float g_V[T_LEN * NKV * HD];     //  8.4 MB
__device__ float g_att[T_LEN * C_DIM];      // 33.5 MB

// ---------------- SGEMM: C[M,N] = A[M,K] * B[K,N], all row-major ------------
// BM=BN=128, BK=16, 256 threads, 8x8 micro-tile, double-buffered smem.
__global__ __launch_bounds__(256) void sgemm128(
    const float* __restrict__ A, const float* __restrict__ B,
    float* __restrict__ C, int M, int N, int K)
{
    __shared__ float As[2][16][128];   // transposed A tile: As[b][k][m]
    __shared__ float Bs[2][16][128];

    const int tid = threadIdx.x;
    const int tx  = tid & 15;       // 0..15 -> 8 cols each
    const int ty  = tid >> 4;       // 0..15 -> 8 rows each
    const int row0 = blockIdx.y << 7;
    const int col0 = blockIdx.x << 7;

    // A loader: 128x16 tile, thread loads rows (tid>>2) and (tid>>2)+64, 4 k's
    const int ar = tid >> 2;
    const int ac = (tid & 3) << 2;
    // B loader: 16x128 tile, thread loads rows (tid>>5), (tid>>5)+8
    const int br = tid >> 5;
    const int bc = (tid & 31) << 2;

    float acc[8][8];
#pragma unroll
    for (int i = 0; i < 8; i++)
#pragma unroll
        for (int j = 0; j < 8; j++) acc[i][j] = 0.f;

    const float* Ab = A + (size_t)row0 * K;
    const float* Bb = B + col0;

    // ---- prologue: load tile 0 into buffer 0 ----
    {
        float4 a0 = *(const float4*)(Ab + (size_t)ar        * K + ac);
        float4 a1 = *(const float4*)(Ab + (size_t)(ar + 64) * K + ac);
        float4 b0 = *(const float4*)(Bb + (size_t)(br)     * N + bc);
        float4 b1 = *(const float4*)(Bb + (size_t)(br + 8) * N + bc);
        As[0][ac + 0][ar] = a0.x; As[0][ac + 1][ar] = a0.y;
        As[0][ac + 2][ar] = a0.z; As[0][ac + 3][ar] = a0.w;
        As[0][ac + 0][ar + 64] = a1.x; As[0][ac + 1][ar + 64] = a1.y;
        As[0][ac + 2][ar + 64] = a1.z; As[0][ac + 3][ar + 64] = a1.w;
        *(float4*)&Bs[0][br][bc]     = b0;
        *(float4*)&Bs[0][br + 8][bc] = b1;
    }
    __syncthreads();

    int buf = 0;
    for (int k0 = 0; k0 < K; k0 += 16) {
        const bool has_next = (k0 + 16) < K;
        float4 a0, a1, b0, b1;
        if (has_next) {                     // issue next-tile global loads early
            const int kn = k0 + 16;
            a0 = *(const float4*)(Ab + (size_t)ar        * K + kn + ac);
            a1 = *(const float4*)(Ab + (size_t)(ar + 64) * K + kn + ac);
            b0 = *(const float4*)(Bb + (size_t)(kn + br)     * N + bc);
            b1 = *(const float4*)(Bb + (size_t)(kn + br + 8) * N + bc);
        }

        // ---- compute on current buffer (overlaps outstanding loads) ----
#pragma unroll
        for (int k = 0; k < 16; k++) {
            float a[8], b[8];
            *(float4*)&a[0] = *(float4*)&As[buf][k][ty * 8];
            *(float4*)&a[4] = *(float4*)&As[buf][k][ty * 8 + 4];
            *(float4*)&b[0] = *(float4*)&Bs[buf][k][tx * 8];
            *(float4*)&b[4] = *(float4*)&Bs[buf][k][tx * 8 + 4];
#pragma unroll
            for (int i = 0; i < 8; i++)
#pragma unroll
                for (int j = 0; j < 8; j++)
                    acc[i][j] += a[i] * b[j];
        }

        if (has_next) {                     // stash into the other buffer
            const int nb = buf ^ 1;
            As[nb][ac + 0][ar] = a0.x; As[nb][ac + 1][ar] = a0.y;
            As[nb][ac + 2][ar] = a0.z; As[nb][ac + 3][ar] = a0.w;
            As[nb][ac + 0][ar + 64] = a1.x; As[nb][ac + 1][ar + 64] = a1.y;
            As[nb][ac + 2][ar + 64] = a1.z; As[nb][ac + 3][ar + 64] = a1.w;
            *(float4*)&Bs[nb][br][bc]     = b0;
            *(float4*)&Bs[nb][br + 8][bc] = b1;
            __syncthreads();
            buf = nb;
        }
    }

#pragma unroll
    for (int i = 0; i < 8; i++) {
        float* Crow = C + (size_t)(row0 + ty * 8 + i) * N + col0 + tx * 8;
        *(float4*)(Crow)     = make_float4(acc[i][0], acc[i][1], acc[i][2], acc[i][3]);
        *(float4*)(Crow + 4) = make_float4(acc[i][4], acc[i][5], acc[i][6], acc[i][7]);
    }
}

// ---------------- RoPE (in place) -------------------------------------------
// data: [T, nheads*128]; pair i in [0,64): (d=i, d=i+64) rotated by ang(t,i).
__global__ __launch_bounds__(256) void rope_kernel(float* __restrict__ data, int nheads)
{
    int idx = blockIdx.x * blockDim.x + threadIdx.x;
    int total = T_LEN * nheads * 64;
    if (idx >= total) return;
    int i  = idx & 63;
    int hd = (idx >> 6) % nheads;
    int t  = idx / (64 * nheads);

    // mirror reference op order: timescale = 10000^(i/64); ang = t / timescale
    float ts  = powf(10000.0f, (float)i * (1.0f / 64.0f));
    float ang = (float)t / ts;
    float s, c;
    sincosf(ang, &s, &c);

    float* p = data + ((size_t)t * nheads + hd) * HD + i;
    float a = p[0];
    float b = p[64];
    p[0]  = a * c - b * s;
    p[64] = b * c + a * s;
}

// ---------------- block-local attention -------------------------------------
// grid: (16 q-tiles, 16 heads, 4 blocks); 256 threads.
// Per CTA: 64 queries x (window of W+64 keys in tiles of 32), online softmax.
#define AQ 64
#define AK 32
#define QS_STRIDE  136   // 136*4 % 16 == 0 -> float4-aligned rows
#define KST_STRIDE 36    // K stored transposed [d][key]
#define VS_STRIDE  132
#define S_STRIDE   33
#define ATTN_SMEM_FLOATS (AQ*QS_STRIDE + HD*KST_STRIDE + AK*VS_STRIDE + AQ*S_STRIDE)

__global__ __launch_bounds__(256) void attn_kernel(
    const float* __restrict__ Qm, const float* __restrict__ Km,
    const float* __restrict__ Vm, float* __restrict__ att)
{
    extern __shared__ float sm[];
    float* Qs  = sm;                          // [AQ][QS_STRIDE]
    float* Kst = Qs + AQ * QS_STRIDE;         // [HD][KST_STRIDE]  (transposed)
    float* Vs  = Kst + HD * KST_STRIDE;       // [AK][VS_STRIDE]
    float* Ss  = Vs + AK * VS_STRIDE;         // [AQ][S_STRIDE]

    const int qt = blockIdx.x;
    const int h  = blockIdx.y;
    const int n  = blockIdx.z;
    const int kvh = h >> 2;                   // GQA: 4 q-heads per kv-head
    const int p0  = qt * AQ;
    const int tid = threadIdx.x;

    // ---- load Q tile [64 x 128] ----
    {
        int r  = tid >> 2;
        int c0 = (tid & 3) * 32;
        const float* src = Qm + (size_t)(n * WW + p0 + r) * C_DIM + h * HD + c0;
#pragma unroll
        for (int u = 0; u < 8; u++)
            *(float4*)&Qs[r * QS_STRIDE + c0 + u * 4] = *(const float4*)(src + u * 4);
    }

    // O-owner mapping: row orow, dims oc*4 + 16u + [0,4)  (bank-conflict-free V reads)
    const int orow = tid >> 2;
    const int oc   = tid & 3;
    // S-compute mapping: 2 rows x 4 keys per thread
    const int srow = (tid >> 3) * 2;
    const int ska  = (tid & 7) * 4;

    float m = -1e20f;   // sentinel > masked(-1e30): keeps exp math branch-free
    float l = 0.f;
    float o[8][4];
#pragma unroll
    for (int u = 0; u < 8; u++)
#pragma unroll
        for (int i = 0; i < 4; i++) o[u][i] = 0.f;

    const float qscale = 0.08838834764831845f;   // 1/sqrt(128)

    // key tile range: j in [p0, p0+1088) covers all valid j for rows [p0,p0+64)
    for (int it = 0; it < 34; it++) {
        const int jt = p0 + it * AK;
        if (n == 0 && jt + AK <= WW) continue;   // fully zero-padded tile (uniform)
        __syncthreads();                          // protect smem reuse

        // ---- load K (transposed) and V tiles, keys jt..jt+31 ----
        {
            int key = tid >> 3;
            int d0  = (tid & 7) * 16;
            int ktg = (n - 1) * WW + jt + key;    // global key time index
            const float* ks = Km + (size_t)ktg * (NKV * HD) + kvh * HD + d0;
            const float* vs = Vm + (size_t)ktg * (NKV * HD) + kvh * HD + d0;
#pragma unroll
            for (int u = 0; u < 4; u++) {
                float4 kv, vv;
                if (ktg >= 0) {
                    kv = *(const float4*)(ks + u * 4);
                    vv = *(const float4*)(vs + u * 4);
                } else {
                    kv = make_float4(0.f, 0.f, 0.f, 0.f);
                    vv = kv;
                }
                Kst[(d0 + u * 4 + 0) * KST_STRIDE + key] = kv.x;
                Kst[(d0 + u * 4 + 1) * KST_STRIDE + key] = kv.y;
                Kst[(d0 + u * 4 + 2) * KST_STRIDE + key] = kv.z;
                Kst[(d0 + u * 4 + 3) * KST_STRIDE + key] = kv.w;
                *(float4*)&Vs[key * VS_STRIDE + d0 + u * 4] = vv;
            }
        }
        __syncthreads();

        // ---- S = Q K^T (masked, scaled) ----
        {
            float acc[2][4];
#pragma unroll
            for (int i = 0; i < 2; i++)
#pragma unroll
                for (int u = 0; u < 4; u++) acc[i][u] = 0.f;
#pragma unroll 4
            for (int d = 0; d < HD; d++) {
                float4 kd = *(const float4*)&Kst[d * KST_STRIDE + ska];
                float q0 = Qs[srow * QS_STRIDE + d];
                float q1 = Qs[(srow + 1) * QS_STRIDE + d];
                acc[0][0] += q0 * kd.x; acc[0][1] += q0 * kd.y;
                acc[0][2] += q0 * kd.z; acc[0][3] += q0 * kd.w;
                acc[1][0] += q1 * kd.x; acc[1][1] += q1 * kd.y;
                acc[1][2] += q1 * kd.z; acc[1][3] += q1 * kd.w;
            }
#pragma unroll
            for (int i = 0; i < 2; i++) {
                int p = p0 + srow + i;
#pragma unroll
                for (int u = 0; u < 4; u++) {
                    int j = jt + ska + u;
                    bool valid = (j >= p) && (j <= p + WW) && (n > 0 || j >= WW);
                    Ss[(srow + i) * S_STRIDE + ska + u] =
                        valid ? acc[i][u] * qscale : -1e30f;
                }
            }
        }
        __syncthreads();

        // ---- online softmax + PV ----
        {
            float sv[AK];
#pragma unroll
            for (int j = 0; j < AK; j++) sv[j] = Ss[orow * S_STRIDE + j];
            float mt = m;
#pragma unroll
            for (int j = 0; j < AK; j++) mt = fmaxf(mt, sv[j]);
            float scale = __expf(m - mt);
            float lsum = 0.f;
#pragma unroll
            for (int j = 0; j < AK; j++) { sv[j] = __expf(sv[j] - mt); lsum += sv[j]; }
            l = l * scale + lsum;
            m = mt;
#pragma unroll
            for (int u = 0; u < 8; u++)
#pragma unroll
                for (int i = 0; i < 4; i++) o[u][i] *= scale;
#pragma unroll 4
            for (int j = 0; j < AK; j++) {
                float p = sv[j];
                const float* vrow = &Vs[j * VS_STRIDE + oc * 4];
#pragma unroll
                for (int u = 0; u < 8; u++) {
                    float4 vv = *(const float4*)(vrow + u * 16);
                    o[u][0] += p * vv.x; o[u][1] += p * vv.y;
                    o[u][2] += p * vv.z; o[u][3] += p * vv.w;
                }
            }
        }
    }

    // ---- normalize + store [T, H*D] ----
    float invl = 1.f / l;
    float* dst = att + (size_t)(n * WW + p0 + orow) * C_DIM + h * HD;
#pragma unroll
    for (int u = 0; u < 8; u++) {
        float4 w = make_float4(o[u][0] * invl, o[u][1] * invl,
                               o[u][2] * invl, o[u][3] * invl);
        *(float4*)(dst + oc * 4 + u * 16) = w;
    }
}

// ---------------- launch ----------------------------------------------------
extern "C" void kernel_launch(void* const* d_in, const int* in_sizes, int n_in,
                              void* d_out, int out_size)
{
    (void)in_sizes; (void)n_in; (void)out_size;
    const float* x  = (const float*)d_in[0];
    const float* qw = (const float*)d_in[1];
    const float* kw = (const float*)d_in[2];
    const float* vw = (const float*)d_in[3];
    const float* ow = (const float*)d_in[4];
    float* out = (float*)d_out;

    float *Qp, *Kp, *Vp, *Ap;
    cudaGetSymbolAddress((void**)&Qp, g_Q);
    cudaGetSymbolAddress((void**)&Kp, g_K);
    cudaGetSymbolAddress((void**)&Vp, g_V);
    cudaGetSymbolAddress((void**)&Ap, g_att);

    const int attn_smem = ATTN_SMEM_FLOATS * (int)sizeof(float);   // 78592 B
    cudaFuncSetAttribute(attn_kernel,
                         cudaFuncAttributeMaxDynamicSharedMemorySize, attn_smem);

    dim3 thr(256);
    // QKV projections
    sgemm128<<<dim3(C_DIM / 128, T_LEN / 128), thr>>>(x, qw, Qp, T_LEN, C_DIM, C_DIM);
    sgemm128<<<dim3((NKV * HD) / 128, T_LEN / 128), thr>>>(x, kw, Kp, T_LEN, NKV * HD, C_DIM);
    sgemm128<<<dim3((NKV * HD) / 128, T_LEN / 128), thr>>>(x, vw, Vp, T_LEN, NKV * HD, C_DIM);
    // RoPE
    rope_kernel<<<(T_LEN * NH  * 64) / 256, 256>>>(Qp, NH);
    rope_kernel<<<(T_LEN * NKV * 64) / 256, 256>>>(Kp, NKV);
    // block-local attention
    attn_kernel<<<dim3(WW / AQ, NH, NB), thr, attn_smem>>>(Qp, Kp, Vp, Ap);
    // output projection
    sgemm128<<<dim3(C_DIM / 128, T_LEN / 128), thr>>>(Ap, ow, out, T_LEN, C_DIM, C_DIM);
}

// round 4
// speedup vs baseline: 1.3833x; 1.3833x over previous
#include <cuda_runtime.h>
#include <cuda_bf16.h>
#include <math.h>
#include <stdint.h>

#define T_LEN 4096
#define C_DIM 2048
#define NH    16
#define NKV   4
#define HD    128
#define WW    1024
#define NB    4

// ---------------- scratch (device globals; no runtime alloc) ----------------
__device__ float g_Q[T_LEN * C_DIM];        // 33.5 MB
__device__ float g_K[T_LEN * NKV * HD];     //  8.4 MB
__device__ float g_V[T_LEN * NKV * HD];     //  8.4 MB
__device__ float g_att[T_LEN * C_DIM];      // 33.5 MB

// ============================================================================
// Tensor-core GEMM: C[M,N] = A[M,K] * B[K,N] fp32 in/out.
// Internally: A,B split to bf16 hi+lo on load; 3 mma passes (HH, HL, LH)
// accumulated in fp32  ->  ~2^-17 relative error (fp32-grade).
// BM=128, BN=128, BK=32, 256 threads (8 warps, warp tile 64x32), double-buffered.
// ============================================================================
#define BM 128
#define BN 128
#define BK 32
#define KST 40                      // smem row stride in bf16 elems (80B = 5*16B)
#define TILE_ELEMS (BM * KST)       // 5120 bf16
#define GEMM_SMEM_BYTES (8 * TILE_ELEMS * 2)   // 81920 B

__device__ __forceinline__ uint32_t sptr(const void* p) {
    return (uint32_t)__cvta_generic_to_shared(p);
}
__device__ __forceinline__ void ldsm4(uint32_t& r0, uint32_t& r1, uint32_t& r2,
                                      uint32_t& r3, uint32_t a) {
    asm volatile("ldmatrix.sync.aligned.m8n8.x4.shared.b16 {%0,%1,%2,%3}, [%4];"
        : "=r"(r0), "=r"(r1), "=r"(r2), "=r"(r3) : "r"(a));
}
__device__ __forceinline__ void ldsm2(uint32_t& r0, uint32_t& r1, uint32_t a) {
    asm volatile("ldmatrix.sync.aligned.m8n8.x2.shared.b16 {%0,%1}, [%2];"
        : "=r"(r0), "=r"(r1) : "r"(a));
}
__device__ __forceinline__ void mma16816(float* c, uint32_t a0, uint32_t a1,
                                         uint32_t a2, uint32_t a3,
                                         uint32_t b0, uint32_t b1) {
    asm volatile(
        "mma.sync.aligned.m16n8k16.row.col.f32.bf16.bf16.f32 "
        "{%0,%1,%2,%3}, {%4,%5,%6,%7}, {%8,%9}, {%0,%1,%2,%3};"
        : "+f"(c[0]), "+f"(c[1]), "+f"(c[2]), "+f"(c[3])
        : "r"(a0), "r"(a1), "r"(a2), "r"(a3), "r"(b0), "r"(b1));
}
__device__ __forceinline__ void split2(float x, float y,
                                       __nv_bfloat162& h, __nv_bfloat162& l) {
    __nv_bfloat16 hx = __float2bfloat16(x);
    __nv_bfloat16 hy = __float2bfloat16(y);
    h.x = hx; h.y = hy;
    l.x = __float2bfloat16(x - __bfloat162float(hx));
    l.y = __float2bfloat16(y - __bfloat162float(hy));
}

__global__ __launch_bounds__(256) void gemm_bf16x(
    const float* __restrict__ A, const float* __restrict__ B,
    float* __restrict__ C, int M, int N, int K)
{
    extern __shared__ __nv_bfloat16 smg[];
    __nv_bfloat16* AsH = smg;                    // [2][BM][KST]
    __nv_bfloat16* AsL = smg + 2 * TILE_ELEMS;
    __nv_bfloat16* BsH = smg + 4 * TILE_ELEMS;   // [2][BN][KST]  (n-major)
    __nv_bfloat16* BsL = smg + 6 * TILE_ELEMS;

    const int tid  = threadIdx.x;
    const int lane = tid & 31;
    const int warp = tid >> 5;
    const int wm = (warp >> 2) * 64;   // warp m-offset: 0 or 64
    const int wn = (warp & 3) * 32;    // warp n-offset: 0..96
    const int row0 = blockIdx.y * BM;
    const int col0 = blockIdx.x * BN;

    // A loader: 4 x float4, rows ar+32u, cols ac..ac+3
    const int ar = tid >> 3;
    const int ac = (tid & 7) * 4;
    // B loader: 16 scalars, col bn, k-chunks bk+8u .. +3
    const int bn = tid & 127;
    const int bk = (tid >> 7) * 4;

    float acc[4][4][4];
#pragma unroll
    for (int a = 0; a < 4; a++)
#pragma unroll
        for (int b = 0; b < 4; b++)
#pragma unroll
            for (int cc = 0; cc < 4; cc++) acc[a][b][cc] = 0.f;

    float4 aS[4];
    float  bS[16];

    // ---- stage loaders ----
    auto load_g = [&](int kk) {
#pragma unroll
        for (int u = 0; u < 4; u++)
            aS[u] = *(const float4*)(A + (size_t)(row0 + ar + u * 32) * K + kk + ac);
#pragma unroll
        for (int u = 0; u < 4; u++)
#pragma unroll
            for (int i = 0; i < 4; i++)
                bS[u * 4 + i] = B[(size_t)(kk + bk + u * 8 + i) * N + col0 + bn];
    };
    auto store_s = [&](int buf) {
        __nv_bfloat16* aH = AsH + buf * TILE_ELEMS;
        __nv_bfloat16* aL = AsL + buf * TILE_ELEMS;
#pragma unroll
        for (int u = 0; u < 4; u++) {
            int idx = (ar + u * 32) * KST + ac;
            __nv_bfloat162 h0, l0, h1, l1;
            split2(aS[u].x, aS[u].y, h0, l0);
            split2(aS[u].z, aS[u].w, h1, l1);
            *(__nv_bfloat162*)(aH + idx)     = h0;
            *(__nv_bfloat162*)(aH + idx + 2) = h1;
            *(__nv_bfloat162*)(aL + idx)     = l0;
            *(__nv_bfloat162*)(aL + idx + 2) = l1;
        }
        __nv_bfloat16* bH = BsH + buf * TILE_ELEMS;
        __nv_bfloat16* bL = BsL + buf * TILE_ELEMS;
#pragma unroll
        for (int u = 0; u < 4; u++) {
            int idx = bn * KST + bk + u * 8;
            __nv_bfloat162 h0, l0, h1, l1;
            split2(bS[u * 4 + 0], bS[u * 4 + 1], h0, l0);
            split2(bS[u * 4 + 2], bS[u * 4 + 3], h1, l1);
            *(__nv_bfloat162*)(bH + idx)     = h0;
            *(__nv_bfloat162*)(bH + idx + 2) = h1;
            *(__nv_bfloat162*)(bL + idx)     = l0;
            *(__nv_bfloat162*)(bL + idx + 2) = l1;
        }
    };

    // ---- prologue ----
    load_g(0);
    store_s(0);
    __syncthreads();

    int buf = 0;
    for (int kk = 0; kk < K; kk += BK) {
        const bool has_next = (kk + BK) < K;
        if (has_next) load_g(kk + BK);

        // ---- compute on current buffer ----
        const __nv_bfloat16* aHb = AsH + buf * TILE_ELEMS;
        const __nv_bfloat16* aLb = AsL + buf * TILE_ELEMS;
        const __nv_bfloat16* bHb = BsH + buf * TILE_ELEMS;
        const __nv_bfloat16* bLb = BsL + buf * TILE_ELEMS;
#pragma unroll
        for (int g = 0; g < 2; g++) {
            const int arow = wm + (lane & 15);
            const int acol = g * 16 + (lane >> 4) * 8;
            const int brow = wn + (lane & 7);
            const int bcol = g * 16 + ((lane >> 3) & 1) * 8;
            uint32_t aHadr = sptr(aHb + arow * KST + acol);
            uint32_t aLadr = sptr(aLb + arow * KST + acol);
            uint32_t bHadr = sptr(bHb + brow * KST + bcol);
            uint32_t bLadr = sptr(bLb + brow * KST + bcol);

            uint32_t aH[4][4], aL[4][4], bH[4][2], bL[4][2];
#pragma unroll
            for (int mf = 0; mf < 4; mf++) {
                ldsm4(aH[mf][0], aH[mf][1], aH[mf][2], aH[mf][3],
                      aHadr + mf * 16 * KST * 2);
                ldsm4(aL[mf][0], aL[mf][1], aL[mf][2], aL[mf][3],
                      aLadr + mf * 16 * KST * 2);
            }
#pragma unroll
            for (int nf = 0; nf < 4; nf++) {
                ldsm2(bH[nf][0], bH[nf][1], bHadr + nf * 8 * KST * 2);
                ldsm2(bL[nf][0], bL[nf][1], bLadr + nf * 8 * KST * 2);
            }
#pragma unroll
            for (int mf = 0; mf < 4; mf++)
#pragma unroll
                for (int nf = 0; nf < 4; nf++) {
                    mma16816(acc[mf][nf], aH[mf][0], aH[mf][1], aH[mf][2], aH[mf][3],
                             bH[nf][0], bH[nf][1]);
                    mma16816(acc[mf][nf], aH[mf][0], aH[mf][1], aH[mf][2], aH[mf][3],
                             bL[nf][0], bL[nf][1]);
                    mma16816(acc[mf][nf], aL[mf][0], aL[mf][1], aL[mf][2], aL[mf][3],
                             bH[nf][0], bH[nf][1]);
                }
        }

        if (has_next) {
            store_s(buf ^ 1);
            __syncthreads();
            buf ^= 1;
        }
    }

    // ---- epilogue: C frag layout c0,c1 -> (m=l/4, n=2(l%4)); c2,c3 -> m+8 ----
#pragma unroll
    for (int mf = 0; mf < 4; mf++)
#pragma unroll
        for (int nf = 0; nf < 4; nf++) {
            int m = row0 + wm + mf * 16 + (lane >> 2);
            int n = col0 + wn + nf * 8 + (lane & 3) * 2;
            *(float2*)(C + (size_t)m * N + n) =
                make_float2(acc[mf][nf][0], acc[mf][nf][1]);
            *(float2*)(C + (size_t)(m + 8) * N + n) =
                make_float2(acc[mf][nf][2], acc[mf][nf][3]);
        }
}

// ---------------- RoPE (in place) -------------------------------------------
__global__ __launch_bounds__(256) void rope_kernel(float* __restrict__ data, int nheads)
{
    int idx = blockIdx.x * blockDim.x + threadIdx.x;
    int total = T_LEN * nheads * 64;
    if (idx >= total) return;
    int i  = idx & 63;
    int hd = (idx >> 6) % nheads;
    int t  = idx / (64 * nheads);

    float ts  = powf(10000.0f, (float)i * (1.0f / 64.0f));
    float ang = (float)t / ts;
    float s, c;
    sincosf(ang, &s, &c);

    float* p = data + ((size_t)t * nheads + hd) * HD + i;
    float a = p[0];
    float b = p[64];
    p[0]  = a * c - b * s;
    p[64] = b * c + a * s;
}

// ---------------- block-local attention (unchanged, passing) ----------------
#define AQ 64
#define AK 32
#define QS_STRIDE  136
#define KST_STRIDE 36
#define VS_STRIDE  132
#define S_STRIDE   33
#define ATTN_SMEM_FLOATS (AQ*QS_STRIDE + HD*KST_STRIDE + AK*VS_STRIDE + AQ*S_STRIDE)

__global__ __launch_bounds__(256) void attn_kernel(
    const float* __restrict__ Qm, const float* __restrict__ Km,
    const float* __restrict__ Vm, float* __restrict__ att)
{
    extern __shared__ float sm[];
    float* Qs  = sm;
    float* Kst = Qs + AQ * QS_STRIDE;
    float* Vs  = Kst + HD * KST_STRIDE;
    float* Ss  = Vs + AK * VS_STRIDE;

    const int qt = blockIdx.x;
    const int h  = blockIdx.y;
    const int n  = blockIdx.z;
    const int kvh = h >> 2;
    const int p0  = qt * AQ;
    const int tid = threadIdx.x;

    {
        int r  = tid >> 2;
        int c0 = (tid & 3) * 32;
        const float* src = Qm + (size_t)(n * WW + p0 + r) * C_DIM + h * HD + c0;
#pragma unroll
        for (int u = 0; u < 8; u++)
            *(float4*)&Qs[r * QS_STRIDE + c0 + u * 4] = *(const float4*)(src + u * 4);
    }

    const int orow = tid >> 2;
    const int oc   = tid & 3;
    const int srow = (tid >> 3) * 2;
    const int ska  = (tid & 7) * 4;

    float m = -1e20f;
    float l = 0.f;
    float o[8][4];
#pragma unroll
    for (int u = 0; u < 8; u++)
#pragma unroll
        for (int i = 0; i < 4; i++) o[u][i] = 0.f;

    const float qscale = 0.08838834764831845f;

    for (int it = 0; it < 34; it++) {
        const int jt = p0 + it * AK;
        if (n == 0 && jt + AK <= WW) continue;
        __syncthreads();

        {
            int key = tid >> 3;
            int d0  = (tid & 7) * 16;
            int ktg = (n - 1) * WW + jt + key;
            const float* ks = Km + (size_t)ktg * (NKV * HD) + kvh * HD + d0;
            const float* vs = Vm + (size_t)ktg * (NKV * HD) + kvh * HD + d0;
#pragma unroll
            for (int u = 0; u < 4; u++) {
                float4 kv, vv;
                if (ktg >= 0) {
                    kv = *(const float4*)(ks + u * 4);
                    vv = *(const float4*)(vs + u * 4);
                } else {
                    kv = make_float4(0.f, 0.f, 0.f, 0.f);
                    vv = kv;
                }
                Kst[(d0 + u * 4 + 0) * KST_STRIDE + key] = kv.x;
                Kst[(d0 + u * 4 + 1) * KST_STRIDE + key] = kv.y;
                Kst[(d0 + u * 4 + 2) * KST_STRIDE + key] = kv.z;
                Kst[(d0 + u * 4 + 3) * KST_STRIDE + key] = kv.w;
                *(float4*)&Vs[key * VS_STRIDE + d0 + u * 4] = vv;
            }
        }
        __syncthreads();

        {
            float acc2[2][4];
#pragma unroll
            for (int i = 0; i < 2; i++)
#pragma unroll
                for (int u = 0; u < 4; u++) acc2[i][u] = 0.f;
#pragma unroll 4
            for (int d = 0; d < HD; d++) {
                float4 kd = *(const float4*)&Kst[d * KST_STRIDE + ska];
                float q0 = Qs[srow * QS_STRIDE + d];
                float q1 = Qs[(srow + 1) * QS_STRIDE + d];
                acc2[0][0] += q0 * kd.x; acc2[0][1] += q0 * kd.y;
                acc2[0][2] += q0 * kd.z; acc2[0][3] += q0 * kd.w;
                acc2[1][0] += q1 * kd.x; acc2[1][1] += q1 * kd.y;
                acc2[1][2] += q1 * kd.z; acc2[1][3] += q1 * kd.w;
            }
#pragma unroll
            for (int i = 0; i < 2; i++) {
                int p = p0 + srow + i;
#pragma unroll
                for (int u = 0; u < 4; u++) {
                    int j = jt + ska + u;
                    bool valid = (j >= p) && (j <= p + WW) && (n > 0 || j >= WW);
                    Ss[(srow + i) * S_STRIDE + ska + u] =
                        valid ? acc2[i][u] * qscale : -1e30f;
                }
            }
        }
        __syncthreads();

        {
            float sv[AK];
#pragma unroll
            for (int j = 0; j < AK; j++) sv[j] = Ss[orow * S_STRIDE + j];
            float mt = m;
#pragma unroll
            for (int j = 0; j < AK; j++) mt = fmaxf(mt, sv[j]);
            float scale = __expf(m - mt);
            float lsum = 0.f;
#pragma unroll
            for (int j = 0; j < AK; j++) { sv[j] = __expf(sv[j] - mt); lsum += sv[j]; }
            l = l * scale + lsum;
            m = mt;
#pragma unroll
            for (int u = 0; u < 8; u++)
#pragma unroll
                for (int i = 0; i < 4; i++) o[u][i] *= scale;
#pragma unroll 4
            for (int j = 0; j < AK; j++) {
                float p = sv[j];
                const float* vrow = &Vs[j * VS_STRIDE + oc * 4];
#pragma unroll
                for (int u = 0; u < 8; u++) {
                    float4 vv = *(const float4*)(vrow + u * 16);
                    o[u][0] += p * vv.x; o[u][1] += p * vv.y;
                    o[u][2] += p * vv.z; o[u][3] += p * vv.w;
                }
            }
        }
    }

    float invl = 1.f / l;
    float* dst = att + (size_t)(n * WW + p0 + orow) * C_DIM + h * HD;
#pragma unroll
    for (int u = 0; u < 8; u++) {
        float4 w = make_float4(o[u][0] * invl, o[u][1] * invl,
                               o[u][2] * invl, o[u][3] * invl);
        *(float4*)(dst + oc * 4 + u * 16) = w;
    }
}

// ---------------- launch ----------------------------------------------------
extern "C" void kernel_launch(void* const* d_in, const int* in_sizes, int n_in,
                              void* d_out, int out_size)
{
    (void)in_sizes; (void)n_in; (void)out_size;
    const float* x  = (const float*)d_in[0];
    const float* qw = (const float*)d_in[1];
    const float* kw = (const float*)d_in[2];
    const float* vw = (const float*)d_in[3];
    const float* ow = (const float*)d_in[4];
    float* out = (float*)d_out;

    float *Qp, *Kp, *Vp, *Ap;
    cudaGetSymbolAddress((void**)&Qp, g_Q);
    cudaGetSymbolAddress((void**)&Kp, g_K);
    cudaGetSymbolAddress((void**)&Vp, g_V);
    cudaGetSymbolAddress((void**)&Ap, g_att);

    const int attn_smem = ATTN_SMEM_FLOATS * (int)sizeof(float);
    cudaFuncSetAttribute(attn_kernel,
                         cudaFuncAttributeMaxDynamicSharedMemorySize, attn_smem);
    cudaFuncSetAttribute(gemm_bf16x,
                         cudaFuncAttributeMaxDynamicSharedMemorySize, GEMM_SMEM_BYTES);

    dim3 thr(256);
    // QKV projections (tensor cores, bf16-split)
    gemm_bf16x<<<dim3(C_DIM / BN, T_LEN / BM), thr, GEMM_SMEM_BYTES>>>(
        x, qw, Qp, T_LEN, C_DIM, C_DIM);
    gemm_bf16x<<<dim3((NKV * HD) / BN, T_LEN / BM), thr, GEMM_SMEM_BYTES>>>(
        x, kw, Kp, T_LEN, NKV * HD, C_DIM);
    gemm_bf16x<<<dim3((NKV * HD) / BN, T_LEN / BM), thr, GEMM_SMEM_BYTES>>>(
        x, vw, Vp, T_LEN, NKV * HD, C_DIM);
    // RoPE
    rope_kernel<<<(T_LEN * NH  * 64) / 256, 256>>>(Qp, NH);
    rope_kernel<<<(T_LEN * NKV * 64) / 256, 256>>>(Kp, NKV);
    // block-local attention
    attn_kernel<<<dim3(WW / AQ, NH, NB), thr, attn_smem>>>(Qp, Kp, Vp, Ap);
    // output projection
    gemm_bf16x<<<dim3(C_DIM / BN, T_LEN / BM), thr, GEMM_SMEM_BYTES>>>(
        Ap, ow, out, T_LEN, C_DIM, C_DIM);
}

// round 5
// speedup vs baseline: 2.4951x; 1.8037x over previous
#include <cuda_runtime.h>
#include <cuda_bf16.h>
#include <math.h>
#include <stdint.h>

#define T_LEN 4096
#define C_DIM 2048
#define NH    16
#define NKV   4
#define HD    128
#define WW    1024
#define NB    4

// ---------------- scratch (device globals; no runtime alloc) ----------------
__device__ float g_Q[T_LEN * C_DIM];
__device__ float g_K[T_LEN * NKV * HD];
__device__ float g_V[T_LEN * NKV * HD];
__device__ float g_att[T_LEN * C_DIM];
__device__ __nv_bfloat16 g_QH[T_LEN * C_DIM];
__device__ __nv_bfloat16 g_QL[T_LEN * C_DIM];
__device__ __nv_bfloat16 g_KH[T_LEN * NKV * HD];
__device__ __nv_bfloat16 g_KL[T_LEN * NKV * HD];
__device__ __nv_bfloat16 g_VH[T_LEN * NKV * HD];
__device__ __nv_bfloat16 g_VL[T_LEN * NKV * HD];

// ---------------- common mma helpers (validated in R4) ----------------------
__device__ __forceinline__ uint32_t sptr(const void* p) {
    return (uint32_t)__cvta_generic_to_shared(p);
}
__device__ __forceinline__ void ldsm4(uint32_t& r0, uint32_t& r1, uint32_t& r2,
                                      uint32_t& r3, uint32_t a) {
    asm volatile("ldmatrix.sync.aligned.m8n8.x4.shared.b16 {%0,%1,%2,%3}, [%4];"
        : "=r"(r0), "=r"(r1), "=r"(r2), "=r"(r3) : "r"(a));
}
__device__ __forceinline__ void ldsm2(uint32_t& r0, uint32_t& r1, uint32_t a) {
    asm volatile("ldmatrix.sync.aligned.m8n8.x2.shared.b16 {%0,%1}, [%2];"
        : "=r"(r0), "=r"(r1) : "r"(a));
}
__device__ __forceinline__ void mma16816(float* c, uint32_t a0, uint32_t a1,
                                         uint32_t a2, uint32_t a3,
                                         uint32_t b0, uint32_t b1) {
    asm volatile(
        "mma.sync.aligned.m16n8k16.row.col.f32.bf16.bf16.f32 "
        "{%0,%1,%2,%3}, {%4,%5,%6,%7}, {%8,%9}, {%0,%1,%2,%3};"
        : "+f"(c[0]), "+f"(c[1]), "+f"(c[2]), "+f"(c[3])
        : "r"(a0), "r"(a1), "r"(a2), "r"(a3), "r"(b0), "r"(b1));
}
__device__ __forceinline__ void split2(float x, float y,
                                       __nv_bfloat162& h, __nv_bfloat162& l) {
    __nv_bfloat16 hx = __float2bfloat16(x);
    __nv_bfloat16 hy = __float2bfloat16(y);
    h.x = hx; h.y = hy;
    l.x = __float2bfloat16(x - __bfloat162float(hx));
    l.y = __float2bfloat16(y - __bfloat162float(hy));
}
__device__ __forceinline__ uint32_t packbf(float x, float y) {
    __nv_bfloat162 v;
    v.x = __float2bfloat16(x);
    v.y = __float2bfloat16(y);
    return *(uint32_t*)&v;
}
__device__ __forceinline__ float ex2(float x) {
    float r;
    asm("ex2.approx.f32 %0, %1;" : "=f"(r) : "f"(x));
    return r;
}

// ============================================================================
// GEMM (unchanged from R4, validated)
// ============================================================================
#define BM 128
#define BN 128
#define BK 32
#define KST 40
#define TILE_ELEMS (BM * KST)
#define GEMM_SMEM_BYTES (8 * TILE_ELEMS * 2)

__global__ __launch_bounds__(256) void gemm_bf16x(
    const float* __restrict__ A, const float* __restrict__ B,
    float* __restrict__ C, int M, int N, int K)
{
    extern __shared__ __nv_bfloat16 smg[];
    __nv_bfloat16* AsH = smg;
    __nv_bfloat16* AsL = smg + 2 * TILE_ELEMS;
    __nv_bfloat16* BsH = smg + 4 * TILE_ELEMS;
    __nv_bfloat16* BsL = smg + 6 * TILE_ELEMS;

    const int tid  = threadIdx.x;
    const int lane = tid & 31;
    const int warp = tid >> 5;
    const int wm = (warp >> 2) * 64;
    const int wn = (warp & 3) * 32;
    const int row0 = blockIdx.y * BM;
    const int col0 = blockIdx.x * BN;

    const int ar = tid >> 3;
    const int ac = (tid & 7) * 4;
    const int bn = tid & 127;
    const int bk = (tid >> 7) * 4;

    float acc[4][4][4];
#pragma unroll
    for (int a = 0; a < 4; a++)
#pragma unroll
        for (int b = 0; b < 4; b++)
#pragma unroll
            for (int cc = 0; cc < 4; cc++) acc[a][b][cc] = 0.f;

    float4 aS[4];
    float  bS[16];

    auto load_g = [&](int kk) {
#pragma unroll
        for (int u = 0; u < 4; u++)
            aS[u] = *(const float4*)(A + (size_t)(row0 + ar + u * 32) * K + kk + ac);
#pragma unroll
        for (int u = 0; u < 4; u++)
#pragma unroll
            for (int i = 0; i < 4; i++)
                bS[u * 4 + i] = B[(size_t)(kk + bk + u * 8 + i) * N + col0 + bn];
    };
    auto store_s = [&](int buf) {
        __nv_bfloat16* aH = AsH + buf * TILE_ELEMS;
        __nv_bfloat16* aL = AsL + buf * TILE_ELEMS;
#pragma unroll
        for (int u = 0; u < 4; u++) {
            int idx = (ar + u * 32) * KST + ac;
            __nv_bfloat162 h0, l0, h1, l1;
            split2(aS[u].x, aS[u].y, h0, l0);
            split2(aS[u].z, aS[u].w, h1, l1);
            *(__nv_bfloat162*)(aH + idx)     = h0;
            *(__nv_bfloat162*)(aH + idx + 2) = h1;
            *(__nv_bfloat162*)(aL + idx)     = l0;
            *(__nv_bfloat162*)(aL + idx + 2) = l1;
        }
        __nv_bfloat16* bH = BsH + buf * TILE_ELEMS;
        __nv_bfloat16* bL = BsL + buf * TILE_ELEMS;
#pragma unroll
        for (int u = 0; u < 4; u++) {
            int idx = bn * KST + bk + u * 8;
            __nv_bfloat162 h0, l0, h1, l1;
            split2(bS[u * 4 + 0], bS[u * 4 + 1], h0, l0);
            split2(bS[u * 4 + 2], bS[u * 4 + 3], h1, l1);
            *(__nv_bfloat162*)(bH + idx)     = h0;
            *(__nv_bfloat162*)(bH + idx + 2) = h1;
            *(__nv_bfloat162*)(bL + idx)     = l0;
            *(__nv_bfloat162*)(bL + idx + 2) = l1;
        }
    };

    load_g(0);
    store_s(0);
    __syncthreads();

    int buf = 0;
    for (int kk = 0; kk < K; kk += BK) {
        const bool has_next = (kk + BK) < K;
        if (has_next) load_g(kk + BK);

        const __nv_bfloat16* aHb = AsH + buf * TILE_ELEMS;
        const __nv_bfloat16* aLb = AsL + buf * TILE_ELEMS;
        const __nv_bfloat16* bHb = BsH + buf * TILE_ELEMS;
        const __nv_bfloat16* bLb = BsL + buf * TILE_ELEMS;
#pragma unroll
        for (int g = 0; g < 2; g++) {
            const int arow = wm + (lane & 15);
            const int acol = g * 16 + (lane >> 4) * 8;
            const int brow = wn + (lane & 7);
            const int bcol = g * 16 + ((lane >> 3) & 1) * 8;
            uint32_t aHadr = sptr(aHb + arow * KST + acol);
            uint32_t aLadr = sptr(aLb + arow * KST + acol);
            uint32_t bHadr = sptr(bHb + brow * KST + bcol);
            uint32_t bLadr = sptr(bLb + brow * KST + bcol);

            uint32_t aH[4][4], aL[4][4], bH[4][2], bL[4][2];
#pragma unroll
            for (int mf = 0; mf < 4; mf++) {
                ldsm4(aH[mf][0], aH[mf][1], aH[mf][2], aH[mf][3],
                      aHadr + mf * 16 * KST * 2);
                ldsm4(aL[mf][0], aL[mf][1], aL[mf][2], aL[mf][3],
                      aLadr + mf * 16 * KST * 2);
            }
#pragma unroll
            for (int nf = 0; nf < 4; nf++) {
                ldsm2(bH[nf][0], bH[nf][1], bHadr + nf * 8 * KST * 2);
                ldsm2(bL[nf][0], bL[nf][1], bLadr + nf * 8 * KST * 2);
            }
#pragma unroll
            for (int mf = 0; mf < 4; mf++)
#pragma unroll
                for (int nf = 0; nf < 4; nf++) {
                    mma16816(acc[mf][nf], aH[mf][0], aH[mf][1], aH[mf][2], aH[mf][3],
                             bH[nf][0], bH[nf][1]);
                    mma16816(acc[mf][nf], aH[mf][0], aH[mf][1], aH[mf][2], aH[mf][3],
                             bL[nf][0], bL[nf][1]);
                    mma16816(acc[mf][nf], aL[mf][0], aL[mf][1], aL[mf][2], aL[mf][3],
                             bH[nf][0], bH[nf][1]);
                }
        }

        if (has_next) {
            store_s(buf ^ 1);
            __syncthreads();
            buf ^= 1;
        }
    }

#pragma unroll
    for (int mf = 0; mf < 4; mf++)
#pragma unroll
        for (int nf = 0; nf < 4; nf++) {
            int m = row0 + wm + mf * 16 + (lane >> 2);
            int n = col0 + wn + nf * 8 + (lane & 3) * 2;
            *(float2*)(C + (size_t)m * N + n) =
                make_float2(acc[mf][nf][0], acc[mf][nf][1]);
            *(float2*)(C + (size_t)(m + 8) * N + n) =
                make_float2(acc[mf][nf][2], acc[mf][nf][3]);
        }
}

// ---------------- RoPE + bf16 hi/lo split ------------------------------------
__global__ __launch_bounds__(256) void rope_split(
    const float* __restrict__ src, __nv_bfloat16* __restrict__ dH,
    __nv_bfloat16* __restrict__ dL, int nheads)
{
    int idx = blockIdx.x * blockDim.x + threadIdx.x;
    int total = T_LEN * nheads * 64;
    if (idx >= total) return;
    int i  = idx & 63;
    int hd = (idx >> 6) % nheads;
    int t  = idx / (64 * nheads);

    float ts  = powf(10000.0f, (float)i * (1.0f / 64.0f));
    float ang = (float)t / ts;
    float s, c;
    sincosf(ang, &s, &c);

    size_t base = ((size_t)t * nheads + hd) * HD + i;
    float a = src[base];
    float b = src[base + 64];
    float r0 = a * c - b * s;
    float r1 = b * c + a * s;

    __nv_bfloat16 h0 = __float2bfloat16(r0);
    __nv_bfloat16 h1 = __float2bfloat16(r1);
    dH[base]      = h0;
    dH[base + 64] = h1;
    dL[base]      = __float2bfloat16(r0 - __bfloat162float(h0));
    dL[base + 64] = __float2bfloat16(r1 - __bfloat162float(h1));
}

// ---------------- V -> bf16 hi/lo --------------------------------------------
__global__ __launch_bounds__(256) void convert_split(
    const float* __restrict__ src, __nv_bfloat16* __restrict__ dH,
    __nv_bfloat16* __restrict__ dL, int total)
{
    int idx = blockIdx.x * blockDim.x + threadIdx.x;
    if (idx >= total) return;
    float v = src[idx];
    __nv_bfloat16 h = __float2bfloat16(v);
    dH[idx] = h;
    dL[idx] = __float2bfloat16(v - __bfloat162float(h));
}

// ============================================================================
// Attention on tensor cores (FA2-style): 4 warps x 16q, 64q x 64k tiles.
// S = QhiKhi+QhiKlo+QloKhi; O += PhiVhi+PhiVlo+PloVhi (all fp32 accum).
// ============================================================================
#define QKSTRIDE 136   // bf16 elems; 272B = 17*16B
#define VTSTRIDE 72    // bf16 elems; 144B = 9*16B
#define SM_QH 0
#define SM_QL 8704
#define SM_KH 17408
#define SM_KL 26112
#define SM_VH 34816
#define SM_VL 44032
#define ATTN_SMEM_ELEMS 53248
#define ATTN_SMEM_BYTES (ATTN_SMEM_ELEMS * 2)   // 106496

__global__ __launch_bounds__(128) void attn_mma(
    const __nv_bfloat16* __restrict__ QH, const __nv_bfloat16* __restrict__ QL,
    const __nv_bfloat16* __restrict__ KH, const __nv_bfloat16* __restrict__ KL,
    const __nv_bfloat16* __restrict__ VH, const __nv_bfloat16* __restrict__ VL,
    float* __restrict__ att)
{
    extern __shared__ __nv_bfloat16 sa[];
    __nv_bfloat16* QsH = sa + SM_QH;   // [64][136]
    __nv_bfloat16* QsL = sa + SM_QL;
    __nv_bfloat16* KsH = sa + SM_KH;   // [64 keys][136]
    __nv_bfloat16* KsL = sa + SM_KL;
    __nv_bfloat16* VtH = sa + SM_VH;   // [128 d][72 keys] (transposed)
    __nv_bfloat16* VtL = sa + SM_VL;

    const int qt = blockIdx.x;          // 0..15
    const int h  = blockIdx.y;          // 0..15
    const int n  = blockIdx.z;          // 0..3
    const int kvh = h >> 2;
    const int p0  = qt * 64;
    const int tid  = threadIdx.x;
    const int lane = tid & 31;
    const int warp = tid >> 5;
    const int wq   = warp * 16;

    // ---- load Q tile [64 rows][128 d] hi/lo ----
    {
        int row = tid >> 1;
        int dh  = (tid & 1) * 64;
        size_t src = ((size_t)(n * WW + p0 + row)) * C_DIM + h * HD + dh;
        int dst = row * QKSTRIDE + dh;
#pragma unroll
        for (int i = 0; i < 8; i++) {
            *(uint4*)(QsH + dst + i * 8) = *(const uint4*)(QH + src + i * 8);
            *(uint4*)(QsL + dst + i * 8) = *(const uint4*)(QL + src + i * 8);
        }
    }

    float o[16][4];
#pragma unroll
    for (int dt = 0; dt < 16; dt++)
#pragma unroll
        for (int c = 0; c < 4; c++) o[dt][c] = 0.f;
    float m0 = -1e30f, m1 = -1e30f, l0 = 0.f, l1 = 0.f;

    // s * (1/sqrt(128)) * log2(e)
    const float SCL = 0.08838834764831845f * 1.4426950408889634f;

    const int kt0 = (n == 0) ? (16 - qt) : 0;

    for (int kt = kt0; kt <= 16; kt++) {
        const int jt  = p0 + kt * 64;              // window coord of tile start
        const int ktg0 = (n - 1) * WW + jt;        // global time of key 0 (>= 0)
        __syncthreads();                            // smem reuse guard

        // ---- load K tile [64][128] hi/lo ----
        {
            int key = tid >> 1;
            int dh  = (tid & 1) * 64;
            size_t src = ((size_t)(ktg0 + key)) * (NKV * HD) + kvh * HD + dh;
            int dst = key * QKSTRIDE + dh;
#pragma unroll
            for (int i = 0; i < 8; i++) {
                *(uint4*)(KsH + dst + i * 8) = *(const uint4*)(KH + src + i * 8);
                *(uint4*)(KsL + dst + i * 8) = *(const uint4*)(KL + src + i * 8);
            }
        }
        // ---- load V tile transposed: Vt[d][key] ----
        {
            int key = tid & 63;
            int dh  = (tid >> 6) * 64;
            size_t src = ((size_t)(ktg0 + key)) * (NKV * HD) + kvh * HD + dh;
#pragma unroll
            for (int i = 0; i < 8; i++) {
                uint4 vh = *(const uint4*)(VH + src + i * 8);
                uint4 vl = *(const uint4*)(VL + src + i * 8);
                const __nv_bfloat16* ph = (const __nv_bfloat16*)&vh;
                const __nv_bfloat16* pl = (const __nv_bfloat16*)&vl;
#pragma unroll
                for (int e = 0; e < 8; e++) {
                    VtH[(dh + i * 8 + e) * VTSTRIDE + key] = ph[e];
                    VtL[(dh + i * 8 + e) * VTSTRIDE + key] = pl[e];
                }
            }
        }
        __syncthreads();

        // ---- S = Q K^T (3-pass split), S[nt] covers keys nt*8..nt*8+7 ----
        float s[8][4];
#pragma unroll
        for (int nt = 0; nt < 8; nt++)
#pragma unroll
            for (int c = 0; c < 4; c++) s[nt][c] = 0.f;

        const int arow = wq + (lane & 15);
        const int acolo = (lane >> 4) * 8;
        const int brow = lane & 7;
        const int bcolo = ((lane >> 3) & 1) * 8;
#pragma unroll
        for (int ks = 0; ks < 8; ks++) {
            uint32_t aH0, aH1, aH2, aH3, aL0, aL1, aL2, aL3;
            ldsm4(aH0, aH1, aH2, aH3,
                  sptr(QsH + arow * QKSTRIDE + ks * 16 + acolo));
            ldsm4(aL0, aL1, aL2, aL3,
                  sptr(QsL + arow * QKSTRIDE + ks * 16 + acolo));
#pragma unroll
            for (int nt = 0; nt < 8; nt++) {
                uint32_t bH0, bH1, bL0, bL1;
                ldsm2(bH0, bH1,
                      sptr(KsH + (nt * 8 + brow) * QKSTRIDE + ks * 16 + bcolo));
                ldsm2(bL0, bL1,
                      sptr(KsL + (nt * 8 + brow) * QKSTRIDE + ks * 16 + bcolo));
                mma16816(s[nt], aH0, aH1, aH2, aH3, bH0, bH1);
                mma16816(s[nt], aH0, aH1, aH2, aH3, bL0, bL1);
                mma16816(s[nt], aL0, aL1, aL2, aL3, bH0, bH1);
            }
        }

        // ---- scale to log2 domain + mask (only first/last tile need it) ----
#pragma unroll
        for (int nt = 0; nt < 8; nt++)
#pragma unroll
            for (int c = 0; c < 4; c++) s[nt][c] *= SCL;

        if (kt == 0 || kt == 16) {
            const bool upper = (kt == 16);
            const int r0 = p0 + wq + (lane >> 2);
            const int r1 = r0 + 8;
#pragma unroll
            for (int nt = 0; nt < 8; nt++) {
                int j0 = jt + nt * 8 + (lane & 3) * 2;
#pragma unroll
                for (int c = 0; c < 2; c++) {
                    int j = j0 + c;
                    bool v0 = upper ? (j <= r0 + WW) : (j >= r0);
                    bool v1 = upper ? (j <= r1 + WW) : (j >= r1);
                    if (!v0) s[nt][c]     = -1e30f;
                    if (!v1) s[nt][c + 2] = -1e30f;
                }
            }
        }

        // ---- online softmax ----
        float nm0 = -1e30f, nm1 = -1e30f;
#pragma unroll
        for (int nt = 0; nt < 8; nt++) {
            nm0 = fmaxf(nm0, fmaxf(s[nt][0], s[nt][1]));
            nm1 = fmaxf(nm1, fmaxf(s[nt][2], s[nt][3]));
        }
#pragma unroll
        for (int off = 1; off <= 2; off <<= 1) {
            nm0 = fmaxf(nm0, __shfl_xor_sync(0xffffffffu, nm0, off));
            nm1 = fmaxf(nm1, __shfl_xor_sync(0xffffffffu, nm1, off));
        }
        nm0 = fmaxf(nm0, m0);
        nm1 = fmaxf(nm1, m1);
        float sc0 = ex2(m0 - nm0);
        float sc1 = ex2(m1 - nm1);

        uint32_t pH[8][2], pL[8][2];
        float ls0 = 0.f, ls1 = 0.f;
#pragma unroll
        for (int nt = 0; nt < 8; nt++) {
            float p00 = ex2(s[nt][0] - nm0);
            float p01 = ex2(s[nt][1] - nm0);
            float p10 = ex2(s[nt][2] - nm1);
            float p11 = ex2(s[nt][3] - nm1);
            ls0 += p00 + p01;
            ls1 += p10 + p11;
            pH[nt][0] = packbf(p00, p01);
            pH[nt][1] = packbf(p10, p11);
            __nv_bfloat162 h0 = *(__nv_bfloat162*)&pH[nt][0];
            __nv_bfloat162 h1 = *(__nv_bfloat162*)&pH[nt][1];
            pL[nt][0] = packbf(p00 - __bfloat162float(h0.x),
                               p01 - __bfloat162float(h0.y));
            pL[nt][1] = packbf(p10 - __bfloat162float(h1.x),
                               p11 - __bfloat162float(h1.y));
        }
#pragma unroll
        for (int off = 1; off <= 2; off <<= 1) {
            ls0 += __shfl_xor_sync(0xffffffffu, ls0, off);
            ls1 += __shfl_xor_sync(0xffffffffu, ls1, off);
        }
        l0 = l0 * sc0 + ls0;
        l1 = l1 * sc1 + ls1;
        m0 = nm0;
        m1 = nm1;
#pragma unroll
        for (int dt = 0; dt < 16; dt++) {
            o[dt][0] *= sc0; o[dt][1] *= sc0;
            o[dt][2] *= sc1; o[dt][3] *= sc1;
        }

        // ---- O += P V (3-pass split); B from Vt[d][key] ----
#pragma unroll
        for (int ks = 0; ks < 4; ks++) {
            uint32_t aH0 = pH[2 * ks][0],     aH1 = pH[2 * ks][1];
            uint32_t aH2 = pH[2 * ks + 1][0], aH3 = pH[2 * ks + 1][1];
            uint32_t aL0 = pL[2 * ks][0],     aL1 = pL[2 * ks][1];
            uint32_t aL2 = pL[2 * ks + 1][0], aL3 = pL[2 * ks + 1][1];
#pragma unroll
            for (int dt = 0; dt < 16; dt++) {
                uint32_t bH0, bH1, bL0, bL1;
                ldsm2(bH0, bH1,
                      sptr(VtH + (dt * 8 + brow) * VTSTRIDE + ks * 16 + bcolo));
                ldsm2(bL0, bL1,
                      sptr(VtL + (dt * 8 + brow) * VTSTRIDE + ks * 16 + bcolo));
                mma16816(o[dt], aH0, aH1, aH2, aH3, bH0, bH1);
                mma16816(o[dt], aH0, aH1, aH2, aH3, bL0, bL1);
                mma16816(o[dt], aL0, aL1, aL2, aL3, bH0, bH1);
            }
        }
    }

    // ---- normalize + store fp32 ----
    float inv0 = 1.f / l0;
    float inv1 = 1.f / l1;
    const int r0 = n * WW + p0 + wq + (lane >> 2);
#pragma unroll
    for (int dt = 0; dt < 16; dt++) {
        int col = h * HD + dt * 8 + (lane & 3) * 2;
        *(float2*)(att + (size_t)r0 * C_DIM + col) =
            make_float2(o[dt][0] * inv0, o[dt][1] * inv0);
        *(float2*)(att + (size_t)(r0 + 8) * C_DIM + col) =
            make_float2(o[dt][2] * inv1, o[dt][3] * inv1);
    }
}

// ---------------- launch ----------------------------------------------------
extern "C" void kernel_launch(void* const* d_in, const int* in_sizes, int n_in,
                              void* d_out, int out_size)
{
    (void)in_sizes; (void)n_in; (void)out_size;
    const float* x  = (const float*)d_in[0];
    const float* qw = (const float*)d_in[1];
    const float* kw = (const float*)d_in[2];
    const float* vw = (const float*)d_in[3];
    const float* ow = (const float*)d_in[4];
    float* out = (float*)d_out;

    float *Qp, *Kp, *Vp, *Ap;
    __nv_bfloat16 *QHp, *QLp, *KHp, *KLp, *VHp, *VLp;
    cudaGetSymbolAddress((void**)&Qp, g_Q);
    cudaGetSymbolAddress((void**)&Kp, g_K);
    cudaGetSymbolAddress((void**)&Vp, g_V);
    cudaGetSymbolAddress((void**)&Ap, g_att);
    cudaGetSymbolAddress((void**)&QHp, g_QH);
    cudaGetSymbolAddress((void**)&QLp, g_QL);
    cudaGetSymbolAddress((void**)&KHp, g_KH);
    cudaGetSymbolAddress((void**)&KLp, g_KL);
    cudaGetSymbolAddress((void**)&VHp, g_VH);
    cudaGetSymbolAddress((void**)&VLp, g_VL);

    cudaFuncSetAttribute(gemm_bf16x,
                         cudaFuncAttributeMaxDynamicSharedMemorySize, GEMM_SMEM_BYTES);
    cudaFuncSetAttribute(attn_mma,
                         cudaFuncAttributeMaxDynamicSharedMemorySize, ATTN_SMEM_BYTES);

    dim3 thr(256);
    // QKV projections (tensor cores, bf16-split)
    gemm_bf16x<<<dim3(C_DIM / BN, T_LEN / BM), thr, GEMM_SMEM_BYTES>>>(
        x, qw, Qp, T_LEN, C_DIM, C_DIM);
    gemm_bf16x<<<dim3((NKV * HD) / BN, T_LEN / BM), thr, GEMM_SMEM_BYTES>>>(
        x, kw, Kp, T_LEN, NKV * HD, C_DIM);
    gemm_bf16x<<<dim3((NKV * HD) / BN, T_LEN / BM), thr, GEMM_SMEM_BYTES>>>(
        x, vw, Vp, T_LEN, NKV * HD, C_DIM);
    // RoPE + hi/lo split
    rope_split<<<(T_LEN * NH  * 64) / 256, 256>>>(Qp, QHp, QLp, NH);
    rope_split<<<(T_LEN * NKV * 64) / 256, 256>>>(Kp, KHp, KLp, NKV);
    convert_split<<<(T_LEN * NKV * HD) / 256, 256>>>(Vp, VHp, VLp, T_LEN * NKV * HD);
    // attention (tensor cores)
    attn_mma<<<dim3(WW / 64, NH, NB), dim3(128), ATTN_SMEM_BYTES>>>(
        QHp, QLp, KHp, KLp, VHp, VLp, Ap);
    // output projection
    gemm_bf16x<<<dim3(C_DIM / BN, T_LEN / BM), thr, GEMM_SMEM_BYTES>>>(
        Ap, ow, out, T_LEN, C_DIM, C_DIM);
}